// round 15
// baseline (speedup 1.0000x reference)
#include <cuda_runtime.h>
#include <stdint.h>
#include <math.h>

#define HH 288
#define WW 288
#define HW (HH*WW)          // 82944
#define NIMG 4              // query b0,b1, key b0,b1
#define HQ 96
#define NPATCH (HQ*HQ)      // 9216
#define DPATCH 144

// ------------------- static device scratch (no allocations allowed) -------------------
__device__ float g_f64a[(size_t)NIMG*64*HW];
__device__ float g_f64b[(size_t)NIMG*64*HW];
__device__ float g_f128[(size_t)NIMG*128*HW];
__device__ float g_f16 [(size_t)NIMG*16*HW];
__device__ float g_patch[(size_t)NIMG*NPATCH*DPATCH]; // [img][patch][144]

__constant__ float c_mean[6] = {0.485f, 0.456f, 0.406f, 0.5f, 0.5f, 0.5f};
__constant__ float c_istd[6] = {1.0f/0.229f, 1.0f/0.224f, 1.0f/0.225f,
                                1.0f/0.1f,   1.0f/0.1f,   1.0f/0.1f};

// ---- cp.async helpers ----
__device__ __forceinline__ void cp_async4(unsigned int dst, const void* src, int src_sz) {
    asm volatile("cp.async.ca.shared.global [%0], [%1], 4, %2;"
                 :: "r"(dst), "l"(src), "r"(src_sz));
}
__device__ __forceinline__ void cp_async16(unsigned int dst, const void* src) {
    asm volatile("cp.async.cg.shared.global [%0], [%1], 16;"
                 :: "r"(dst), "l"(src));
}
__device__ __forceinline__ void cp_commit() {
    asm volatile("cp.async.commit_group;");
}
__device__ __forceinline__ void cp_wait1() {
    asm volatile("cp.async.wait_group 1;");
}
__device__ __forceinline__ void cp_wait2() {
    asm volatile("cp.async.wait_group 2;");
}

#define CTILE (34*34)

// ------------------- conv1: 6->64, MeanShift fused at load, ReLU -------------------
// grid: (9, 9, NIMG*4)  block: (32, 8)
__global__ __launch_bounds__(256, 2)
void k_conv1(const float* __restrict__ qsrc, const float* __restrict__ ksrc,
             const float* __restrict__ w, const float* __restrict__ bias,
             float* __restrict__ out) {
    __shared__ float tile[6*CTILE];          // 27.7 KB
    __shared__ float w_s[6*144];             // [cin][kk*16 + oc]

    const int tx = threadIdx.x, ty = threadIdx.y;
    const int tid = ty * 32 + tx;
    const int img = blockIdx.z >> 2;
    const int cg  = blockIdx.z & 3;
    const int bx = blockIdx.x * 32, by = blockIdx.y * 32;

    const float* in = (img < 2) ? (qsrc + (size_t)img*6*HW)
                                : (ksrc + (size_t)(img-2)*6*HW);

#pragma unroll
    for (int t = 0; t < 5; ++t) {
        int i = tid + t*256;
        if (i >= CTILE) break;
        int r = i / 34, c = i - r*34;
        int gy = by - 1 + r, gx = bx - 1 + c;
        bool ok = (gy >= 0) & (gy < HH) & (gx >= 0) & (gx < WW);
        int off = min(max(gy, 0), HH-1)*WW + min(max(gx, 0), WW-1);
#pragma unroll
        for (int ch = 0; ch < 6; ++ch) {
            float v = ok ? (in[(size_t)ch*HW + off] - c_mean[ch]) * c_istd[ch] : 0.0f;
            tile[ch*CTILE + i] = v;
        }
    }
    for (int idx = tid; idx < 6*144; idx += 256) {
        int cin = idx / 144, r = idx % 144;
        int kk = r >> 4, oc = r & 15;
        w_s[idx] = w[((size_t)(cg*16 + oc) * 6 + cin) * 9 + kk];
    }
    __syncthreads();

    float acc[16][4];
#pragma unroll
    for (int oc = 0; oc < 16; ++oc)
#pragma unroll
        for (int p = 0; p < 4; ++p) acc[oc][p] = 0.0f;

#pragma unroll
    for (int ch = 0; ch < 6; ++ch) {
        const float*  T  = &tile[ch*CTILE];
        const float4* W4 = (const float4*)&w_s[ch*144];
#pragma unroll
        for (int kh = 0; kh < 3; ++kh) {
#pragma unroll
            for (int kw = 0; kw < 3; ++kw) {
                const int kk = kh*3 + kw;
                float v0 = T[(ty      + kh)*34 + tx + kw];
                float v1 = T[(ty +  8 + kh)*34 + tx + kw];
                float v2 = T[(ty + 16 + kh)*34 + tx + kw];
                float v3 = T[(ty + 24 + kh)*34 + tx + kw];
#pragma unroll
                for (int q = 0; q < 4; ++q) {
                    float4 wq = W4[kk*4 + q];
                    acc[q*4+0][0] += v0*wq.x; acc[q*4+0][1] += v1*wq.x;
                    acc[q*4+0][2] += v2*wq.x; acc[q*4+0][3] += v3*wq.x;
                    acc[q*4+1][0] += v0*wq.y; acc[q*4+1][1] += v1*wq.y;
                    acc[q*4+1][2] += v2*wq.y; acc[q*4+1][3] += v3*wq.y;
                    acc[q*4+2][0] += v0*wq.z; acc[q*4+2][1] += v1*wq.z;
                    acc[q*4+2][2] += v2*wq.z; acc[q*4+2][3] += v3*wq.z;
                    acc[q*4+3][0] += v0*wq.w; acc[q*4+3][1] += v1*wq.w;
                    acc[q*4+3][2] += v2*wq.w; acc[q*4+3][3] += v3*wq.w;
                }
            }
        }
    }

#pragma unroll
    for (int oc = 0; oc < 16; ++oc) {
        int ocg = cg*16 + oc;
        float bv = bias[ocg];
#pragma unroll
        for (int p = 0; p < 4; ++p) {
            int y = by + ty + p*8;
            float v = acc[oc][p] + bv;
            v = fmaxf(v, 0.0f);
            out[((size_t)(img*64 + ocg)) * HW + y*WW + bx + tx] = v;
        }
    }
}

// ------------------- 3x3 conv, pad=1, ReLU (R7-proven) -------------------
template<int CIN, int COUT>
__global__ __launch_bounds__(256, 2)
void k_conv3x3(const float* __restrict__ in, const float* __restrict__ w,
               const float* __restrict__ bias, float* __restrict__ out) {
    __shared__ float tile[4][2*CTILE];
    __shared__ float w_all[CIN*144];

    const int tx = threadIdx.x, ty = threadIdx.y;
    const int tid = ty * 32 + tx;
    const int groups = COUT / 16;
    const int img = blockIdx.z / groups;
    const int cg  = blockIdx.z % groups;
    const int bx = blockIdx.x * 32, by = blockIdx.y * 32;
    const int S = CIN / 2;

    unsigned int tile_base = (unsigned int)__cvta_generic_to_shared(&tile[0][0]);
    unsigned int w_base    = (unsigned int)__cvta_generic_to_shared(&w_all[0]);

    const bool has5 = (tid < CTILE - 4*256);   // 132
    int  g_off[5];
    int  sz  [5];
    unsigned int s_off[5];
#pragma unroll
    for (int t = 0; t < 5; ++t) {
        int i = tid + t*256;
        if (i >= CTILE) i = 0;
        int r = i / 34, c = i - r*34;
        int gy = by - 1 + r, gx = bx - 1 + c;
        bool ok = (gy >= 0) & (gy < HH) & (gx >= 0) & (gx < WW);
        int cy = min(max(gy, 0), HH-1), cx = min(max(gx, 0), WW-1);
        g_off[t] = cy*WW + cx;
        sz  [t] = ok ? 4 : 0;
        s_off[t] = (unsigned)i * 4u;
    }

    float acc[16][4];
#pragma unroll
    for (int oc = 0; oc < 16; ++oc)
#pragma unroll
        for (int p = 0; p < 4; ++p) acc[oc][p] = 0.0f;

    auto issue_stage = [&](int st) {
        int buf = st & 3;
        const float* inp0 = in + ((size_t)(img*CIN + st*2)) * HW;
#pragma unroll
        for (int ch = 0; ch < 2; ++ch) {
            const float* inp = inp0 + (size_t)ch * HW;
            unsigned int tb = tile_base + (buf*2 + ch) * (CTILE*4);
#pragma unroll
            for (int t = 0; t < 4; ++t)
                cp_async4(tb + s_off[t], inp + g_off[t], sz[t]);
            if (has5)
                cp_async4(tb + s_off[4], inp + g_off[4], sz[4]);
        }
    };

    for (int idx = tid; idx < CIN*144; idx += 256) {
        int cin = idx / 144, r = idx % 144;
        int kk = r >> 4, oc = r & 15;
        cp_async4(w_base + idx*4, w + ((size_t)(cg*16 + oc) * CIN + cin) * 9 + kk, 4);
    }
    issue_stage(0);
    cp_commit();
    if (S > 1) issue_stage(1);
    cp_commit();
    if (S > 2) issue_stage(2);
    cp_commit();

    for (int s = 0; s < S; ++s) {
        cp_wait2();
        __syncthreads();
        if (s + 3 < S) issue_stage(s + 3);
        cp_commit();

        const int buf = s & 3;
#pragma unroll
        for (int ch = 0; ch < 2; ++ch) {
            const float*  T  = &tile[buf][ch*CTILE];
            const float4* W4 = (const float4*)&w_all[(s*2 + ch)*144];
#pragma unroll
            for (int kh = 0; kh < 3; ++kh) {
#pragma unroll
                for (int kw = 0; kw < 3; ++kw) {
                    const int kk = kh*3 + kw;
                    float v0 = T[(ty      + kh)*34 + tx + kw];
                    float v1 = T[(ty +  8 + kh)*34 + tx + kw];
                    float v2 = T[(ty + 16 + kh)*34 + tx + kw];
                    float v3 = T[(ty + 24 + kh)*34 + tx + kw];
#pragma unroll
                    for (int q = 0; q < 4; ++q) {
                        float4 wq = W4[kk*4 + q];
                        acc[q*4+0][0] += v0*wq.x; acc[q*4+0][1] += v1*wq.x;
                        acc[q*4+0][2] += v2*wq.x; acc[q*4+0][3] += v3*wq.x;
                        acc[q*4+1][0] += v0*wq.y; acc[q*4+1][1] += v1*wq.y;
                        acc[q*4+1][2] += v2*wq.y; acc[q*4+1][3] += v3*wq.y;
                        acc[q*4+2][0] += v0*wq.z; acc[q*4+2][1] += v1*wq.z;
                        acc[q*4+2][2] += v2*wq.z; acc[q*4+2][3] += v3*wq.z;
                        acc[q*4+3][0] += v0*wq.w; acc[q*4+3][1] += v1*wq.w;
                        acc[q*4+3][2] += v2*wq.w; acc[q*4+3][3] += v3*wq.w;
                    }
                }
            }
        }
    }

#pragma unroll
    for (int oc = 0; oc < 16; ++oc) {
        int ocg = cg*16 + oc;
        float bv = bias[ocg];
#pragma unroll
        for (int p = 0; p < 4; ++p) {
            int y = by + ty + p*8;
            float v = acc[oc][p] + bv;
            v = fmaxf(v, 0.0f);
            out[((size_t)(img*COUT + ocg)) * HW + y*WW + bx + tx] = v;
        }
    }
}

// ------------------- 1x1 conv 128->16 + leaky_relu(0.2), float2 + MLP4 ----------
__global__ __launch_bounds__(256)
void k_conv4(const float* __restrict__ w4, const float* __restrict__ b4) {
    __shared__ float ws[16*128];
    __shared__ float bs[16];
    int tid = threadIdx.x;
    for (int i = tid; i < 16*128; i += 256) ws[i] = w4[i];
    if (tid < 16) bs[tid] = b4[tid];
    __syncthreads();

    int p2 = blockIdx.x * 256 + tid;         // float2 index (HW/2 per img)
    int img = blockIdx.y;

    float2 acc[16];
#pragma unroll
    for (int c = 0; c < 16; ++c) acc[c] = make_float2(bs[c], bs[c]);

    const float2* in = (const float2*)(g_f128 + (size_t)img*128*HW) + p2;
    for (int ci = 0; ci < 128; ci += 4) {
        float2 v0 = in[(size_t)(ci + 0) * (HW/2)];
        float2 v1 = in[(size_t)(ci + 1) * (HW/2)];
        float2 v2 = in[(size_t)(ci + 2) * (HW/2)];
        float2 v3 = in[(size_t)(ci + 3) * (HW/2)];
#pragma unroll
        for (int c = 0; c < 16; ++c) {
            float w0 = ws[c*128 + ci], w1 = ws[c*128 + ci + 1];
            float w2 = ws[c*128 + ci + 2], w3 = ws[c*128 + ci + 3];
            acc[c].x += w0*v0.x + w1*v1.x + w2*v2.x + w3*v3.x;
            acc[c].y += w0*v0.y + w1*v1.y + w2*v2.y + w3*v3.y;
        }
    }
    float2* out = (float2*)(g_f16 + (size_t)img*16*HW) + p2;
#pragma unroll
    for (int c = 0; c < 16; ++c) {
        float2 v = acc[c];
        v.x = (v.x > 0.0f) ? v.x : 0.2f*v.x;
        v.y = (v.y > 0.0f) ? v.y : 0.2f*v.y;
        out[(size_t)c * (HW/2)] = v;
    }
}

// ------------------- unfold k3s3 + per-patch L2 normalize -------------------
__global__ void k_patch() {
    int gw = (blockIdx.x * blockDim.x + threadIdx.x) >> 5;
    int lane = threadIdx.x & 31;
    if (gw >= NIMG * NPATCH) return;
    int img = gw / NPATCH;
    int p   = gw % NPATCH;
    int hq = p / HQ, wq = p % HQ;
    const float* f = g_f16 + (size_t)img*16*HW;

    float v[5];
    float ss = 0.0f;
#pragma unroll
    for (int t = 0; t < 5; ++t) {
        int d = lane + t*32;
        float x = 0.0f;
        if (d < DPATCH) {
            int c = d / 9, kk = d % 9;
            int y = hq*3 + kk/3, xx = wq*3 + kk%3;
            x = f[(size_t)c*HW + y*WW + xx];
        }
        v[t] = x;
        ss += x * x;
    }
#pragma unroll
    for (int m = 16; m; m >>= 1) ss += __shfl_xor_sync(0xffffffffu, ss, m);
    float inv = 1.0f / fmaxf(sqrtf(ss), 1e-12f);
    float* o = g_patch + ((size_t)img*NPATCH + p) * DPATCH;
#pragma unroll
    for (int t = 0; t < 5; ++t) {
        int d = lane + t*32;
        if (d < DPATCH) o[d] = v[t] * inv;
    }
}

// ------------------- correlation GEMM fused with max/argmax over keys -------------------
// grid: (72 m-tiles, 2 batches)  block: 512 (128 queries x 128 keys, 4q x 8k per thread)
// 16 warps/SM (was 8) to hide LDS/barrier stalls; same smem, same lane mapping as R7.
#define KPAD 37
#define KTILES 72
__global__ __launch_bounds__(512, 1)
void k_corr(float* __restrict__ out, int out_size) {
    extern __shared__ float4 sm[];
    float4* q_s = sm;                        // 128*36
    float4* k_s = sm + 128*36;               // 2 * 128*KPAD

    const int tid = threadIdx.x;
    const int b = blockIdx.y;
    const int mt = blockIdx.x;
    const float4* qg = (const float4*)(g_patch + (size_t)b       * NPATCH * DPATCH);
    const float4* kg = (const float4*)(g_patch + (size_t)(2 + b) * NPATCH * DPATCH);

    unsigned int q_base = (unsigned int)__cvta_generic_to_shared(q_s);
    unsigned int k_base = (unsigned int)__cvta_generic_to_shared(k_s);

    auto issue_k = [&](int bb, int kt) {
        unsigned int base = k_base + bb * (128*KPAD*16);
        const float4* src = kg + (size_t)kt * 128 * 36;
        for (int i = tid; i < 128*36; i += 512) {
            int r = i / 36, c = i % 36;
            cp_async16(base + (r*KPAD + c)*16, src + i);
        }
    };

    {   // q tile (rows contiguous, no pad)
        const float4* src = qg + (size_t)mt * 128 * 36;
        for (int i = tid; i < 128*36; i += 512)
            cp_async16(q_base + i*16, src + i);
    }
    issue_k(0, 0);
    cp_commit();
    issue_k(1, 1);
    cp_commit();

    const int qgrp = tid >> 4;    // 0..31: owns q rows qgrp*4..+3
    const int kgrp = tid & 15;    // 0..15: owns k rows j*16+kgrp, j=0..7

    float rmax[4];
    int   ridx[4];
#pragma unroll
    for (int i = 0; i < 4; ++i) { rmax[i] = -1e30f; ridx[i] = 0x7fffffff; }

    for (int kt = 0; kt < KTILES; ++kt) {
        cp_wait1();
        __syncthreads();

        const float4* kb = k_s + (kt & 1) * (128*KPAD);

        float acc[8][4];
#pragma unroll
        for (int j = 0; j < 8; ++j)
#pragma unroll
            for (int i = 0; i < 4; ++i) acc[j][i] = 0.0f;

        for (int c = 0; c < 36; ++c) {
            float4 qv[4];
#pragma unroll
            for (int i = 0; i < 4; ++i) qv[i] = q_s[(qgrp*4 + i)*36 + c];
#pragma unroll
            for (int j = 0; j < 8; ++j) {
                float4 kv = kb[(j*16 + kgrp)*KPAD + c];
#pragma unroll
                for (int i = 0; i < 4; ++i)
                    acc[j][i] += qv[i].x*kv.x + qv[i].y*kv.y
                               + qv[i].z*kv.z + qv[i].w*kv.w;
            }
        }

#pragma unroll
        for (int i = 0; i < 4; ++i) {
#pragma unroll
            for (int j = 0; j < 8; ++j) {
                if (acc[j][i] > rmax[i]) { rmax[i] = acc[j][i]; ridx[i] = kt*128 + j*16 + kgrp; }
            }
        }

        __syncthreads();
        if (kt + 2 < KTILES) issue_k(kt & 1, kt + 2);
        cp_commit();
    }

    // reduce across the 16 lanes sharing each q row (kgrp dimension)
#pragma unroll
    for (int i = 0; i < 4; ++i) {
        float bv = rmax[i];
        int   bi = ridx[i];
#pragma unroll
        for (int m = 8; m; m >>= 1) {
            float ov = __shfl_xor_sync(0xffffffffu, bv, m);
            int   oi = __shfl_xor_sync(0xffffffffu, bi, m);
            if (ov > bv || (ov == bv && oi < bi)) { bv = ov; bi = oi; }
        }
        if (kgrp == 0) {
            int m = mt*128 + qgrp*4 + i;
            out[b*NPATCH + m] = bv;
            if (out_size >= 4*NPATCH)
                out[2*NPATCH + b*NPATCH + m] = (float)bi;
        }
    }
}

// ------------------- launch -------------------
extern "C" void kernel_launch(void* const* d_in, const int* in_sizes, int n_in,
                              void* d_out, int out_size) {
    const float* query = (const float*)d_in[0];
    const float* key   = (const float*)d_in[1];
    const float* w1 = (const float*)d_in[3];  const float* b1 = (const float*)d_in[4];
    const float* w2 = (const float*)d_in[5];  const float* b2 = (const float*)d_in[6];
    const float* w3 = (const float*)d_in[7];  const float* b3 = (const float*)d_in[8];
    const float* w4 = (const float*)d_in[9];  const float* b4 = (const float*)d_in[10];
    float* out = (float*)d_out;

    float *p_a, *p_b, *p_128;
    cudaGetSymbolAddress((void**)&p_a,    g_f64a);
    cudaGetSymbolAddress((void**)&p_b,    g_f64b);
    cudaGetSymbolAddress((void**)&p_128,  g_f128);

    const int corr_smem = (128*36 + 2*128*KPAD) * (int)sizeof(float4);  // 225280 B
    cudaFuncSetAttribute(k_corr, cudaFuncAttributeMaxDynamicSharedMemorySize, corr_smem);

    dim3 blk(32, 8);
    k_conv1<<<dim3(9, 9, NIMG*4), blk>>>(query, key, w1, b1, p_a);
    k_conv3x3<64, 64><<<dim3(9, 9, NIMG*4),  blk>>>(p_a, w2, b2, p_b);
    k_conv3x3<64,128><<<dim3(9, 9, NIMG*8),  blk>>>(p_b, w3, b3, p_128);

    k_conv4<<<dim3(HW/512, NIMG), 256>>>(w4, b4);

    k_patch<<<(NIMG*NPATCH*32 + 255)/256, 256>>>();

    k_corr<<<dim3(NPATCH/128, 2), 512, corr_smem>>>(out, out_size);
}

// round 16
// speedup vs baseline: 1.6359x; 1.6359x over previous
#include <cuda_runtime.h>
#include <stdint.h>
#include <math.h>

#define HH 288
#define WW 288
#define HW (HH*WW)          // 82944
#define NIMG 4              // query b0,b1, key b0,b1
#define HQ 96
#define NPATCH (HQ*HQ)      // 9216
#define DPATCH 144

// ------------------- static device scratch (no allocations allowed) -------------------
__device__ float g_f64a[(size_t)NIMG*64*HW];
__device__ float g_f64b[(size_t)NIMG*64*HW];
__device__ float g_f128[(size_t)NIMG*128*HW];
__device__ float g_f16 [(size_t)NIMG*16*HW];
__device__ float g_patch[(size_t)NIMG*NPATCH*DPATCH]; // [img][patch][144]

__constant__ float c_mean[6] = {0.485f, 0.456f, 0.406f, 0.5f, 0.5f, 0.5f};
__constant__ float c_istd[6] = {1.0f/0.229f, 1.0f/0.224f, 1.0f/0.225f,
                                1.0f/0.1f,   1.0f/0.1f,   1.0f/0.1f};

// ---- cp.async helpers ----
__device__ __forceinline__ void cp_async4(unsigned int dst, const void* src, int src_sz) {
    asm volatile("cp.async.ca.shared.global [%0], [%1], 4, %2;"
                 :: "r"(dst), "l"(src), "r"(src_sz));
}
__device__ __forceinline__ void cp_async16(unsigned int dst, const void* src) {
    asm volatile("cp.async.cg.shared.global [%0], [%1], 16;"
                 :: "r"(dst), "l"(src));
}
__device__ __forceinline__ void cp_commit() {
    asm volatile("cp.async.commit_group;");
}
__device__ __forceinline__ void cp_wait1() {
    asm volatile("cp.async.wait_group 1;");
}
__device__ __forceinline__ void cp_wait2() {
    asm volatile("cp.async.wait_group 2;");
}

#define CTILE (34*34)

// ------------------- conv1: 6->64, MeanShift fused at load, ReLU -------------------
// grid: (9, 9, NIMG*4)  block: (32, 8)
__global__ __launch_bounds__(256, 2)
void k_conv1(const float* __restrict__ qsrc, const float* __restrict__ ksrc,
             const float* __restrict__ w, const float* __restrict__ bias,
             float* __restrict__ out) {
    __shared__ float tile[6*CTILE];          // 27.7 KB
    __shared__ float w_s[6*144];             // [cin][kk*16 + oc]

    const int tx = threadIdx.x, ty = threadIdx.y;
    const int tid = ty * 32 + tx;
    const int img = blockIdx.z >> 2;
    const int cg  = blockIdx.z & 3;
    const int bx = blockIdx.x * 32, by = blockIdx.y * 32;

    const float* in = (img < 2) ? (qsrc + (size_t)img*6*HW)
                                : (ksrc + (size_t)(img-2)*6*HW);

#pragma unroll
    for (int t = 0; t < 5; ++t) {
        int i = tid + t*256;
        if (i >= CTILE) break;
        int r = i / 34, c = i - r*34;
        int gy = by - 1 + r, gx = bx - 1 + c;
        bool ok = (gy >= 0) & (gy < HH) & (gx >= 0) & (gx < WW);
        int off = min(max(gy, 0), HH-1)*WW + min(max(gx, 0), WW-1);
#pragma unroll
        for (int ch = 0; ch < 6; ++ch) {
            float v = ok ? (in[(size_t)ch*HW + off] - c_mean[ch]) * c_istd[ch] : 0.0f;
            tile[ch*CTILE + i] = v;
        }
    }
    for (int idx = tid; idx < 6*144; idx += 256) {
        int cin = idx / 144, r = idx % 144;
        int kk = r >> 4, oc = r & 15;
        w_s[idx] = w[((size_t)(cg*16 + oc) * 6 + cin) * 9 + kk];
    }
    __syncthreads();

    float acc[16][4];
#pragma unroll
    for (int oc = 0; oc < 16; ++oc)
#pragma unroll
        for (int p = 0; p < 4; ++p) acc[oc][p] = 0.0f;

#pragma unroll
    for (int ch = 0; ch < 6; ++ch) {
        const float*  T  = &tile[ch*CTILE];
        const float4* W4 = (const float4*)&w_s[ch*144];
#pragma unroll
        for (int kh = 0; kh < 3; ++kh) {
#pragma unroll
            for (int kw = 0; kw < 3; ++kw) {
                const int kk = kh*3 + kw;
                float v0 = T[(ty      + kh)*34 + tx + kw];
                float v1 = T[(ty +  8 + kh)*34 + tx + kw];
                float v2 = T[(ty + 16 + kh)*34 + tx + kw];
                float v3 = T[(ty + 24 + kh)*34 + tx + kw];
#pragma unroll
                for (int q = 0; q < 4; ++q) {
                    float4 wq = W4[kk*4 + q];
                    acc[q*4+0][0] += v0*wq.x; acc[q*4+0][1] += v1*wq.x;
                    acc[q*4+0][2] += v2*wq.x; acc[q*4+0][3] += v3*wq.x;
                    acc[q*4+1][0] += v0*wq.y; acc[q*4+1][1] += v1*wq.y;
                    acc[q*4+1][2] += v2*wq.y; acc[q*4+1][3] += v3*wq.y;
                    acc[q*4+2][0] += v0*wq.z; acc[q*4+2][1] += v1*wq.z;
                    acc[q*4+2][2] += v2*wq.z; acc[q*4+2][3] += v3*wq.z;
                    acc[q*4+3][0] += v0*wq.w; acc[q*4+3][1] += v1*wq.w;
                    acc[q*4+3][2] += v2*wq.w; acc[q*4+3][3] += v3*wq.w;
                }
            }
        }
    }

#pragma unroll
    for (int oc = 0; oc < 16; ++oc) {
        int ocg = cg*16 + oc;
        float bv = bias[ocg];
#pragma unroll
        for (int p = 0; p < 4; ++p) {
            int y = by + ty + p*8;
            float v = acc[oc][p] + bv;
            v = fmaxf(v, 0.0f);
            out[((size_t)(img*64 + ocg)) * HW + y*WW + bx + tx] = v;
        }
    }
}

// ------------------- 3x3 conv, pad=1, ReLU (R7-proven) -------------------
template<int CIN, int COUT>
__global__ __launch_bounds__(256, 2)
void k_conv3x3(const float* __restrict__ in, const float* __restrict__ w,
               const float* __restrict__ bias, float* __restrict__ out) {
    __shared__ float tile[4][2*CTILE];
    __shared__ float w_all[CIN*144];

    const int tx = threadIdx.x, ty = threadIdx.y;
    const int tid = ty * 32 + tx;
    const int groups = COUT / 16;
    const int img = blockIdx.z / groups;
    const int cg  = blockIdx.z % groups;
    const int bx = blockIdx.x * 32, by = blockIdx.y * 32;
    const int S = CIN / 2;

    unsigned int tile_base = (unsigned int)__cvta_generic_to_shared(&tile[0][0]);
    unsigned int w_base    = (unsigned int)__cvta_generic_to_shared(&w_all[0]);

    const bool has5 = (tid < CTILE - 4*256);   // 132
    int  g_off[5];
    int  sz  [5];
    unsigned int s_off[5];
#pragma unroll
    for (int t = 0; t < 5; ++t) {
        int i = tid + t*256;
        if (i >= CTILE) i = 0;
        int r = i / 34, c = i - r*34;
        int gy = by - 1 + r, gx = bx - 1 + c;
        bool ok = (gy >= 0) & (gy < HH) & (gx >= 0) & (gx < WW);
        int cy = min(max(gy, 0), HH-1), cx = min(max(gx, 0), WW-1);
        g_off[t] = cy*WW + cx;
        sz  [t] = ok ? 4 : 0;
        s_off[t] = (unsigned)i * 4u;
    }

    float acc[16][4];
#pragma unroll
    for (int oc = 0; oc < 16; ++oc)
#pragma unroll
        for (int p = 0; p < 4; ++p) acc[oc][p] = 0.0f;

    auto issue_stage = [&](int st) {
        int buf = st & 3;
        const float* inp0 = in + ((size_t)(img*CIN + st*2)) * HW;
#pragma unroll
        for (int ch = 0; ch < 2; ++ch) {
            const float* inp = inp0 + (size_t)ch * HW;
            unsigned int tb = tile_base + (buf*2 + ch) * (CTILE*4);
#pragma unroll
            for (int t = 0; t < 4; ++t)
                cp_async4(tb + s_off[t], inp + g_off[t], sz[t]);
            if (has5)
                cp_async4(tb + s_off[4], inp + g_off[4], sz[4]);
        }
    };

    for (int idx = tid; idx < CIN*144; idx += 256) {
        int cin = idx / 144, r = idx % 144;
        int kk = r >> 4, oc = r & 15;
        cp_async4(w_base + idx*4, w + ((size_t)(cg*16 + oc) * CIN + cin) * 9 + kk, 4);
    }
    issue_stage(0);
    cp_commit();
    if (S > 1) issue_stage(1);
    cp_commit();
    if (S > 2) issue_stage(2);
    cp_commit();

    for (int s = 0; s < S; ++s) {
        cp_wait2();
        __syncthreads();
        if (s + 3 < S) issue_stage(s + 3);
        cp_commit();

        const int buf = s & 3;
#pragma unroll
        for (int ch = 0; ch < 2; ++ch) {
            const float*  T  = &tile[buf][ch*CTILE];
            const float4* W4 = (const float4*)&w_all[(s*2 + ch)*144];
#pragma unroll
            for (int kh = 0; kh < 3; ++kh) {
#pragma unroll
                for (int kw = 0; kw < 3; ++kw) {
                    const int kk = kh*3 + kw;
                    float v0 = T[(ty      + kh)*34 + tx + kw];
                    float v1 = T[(ty +  8 + kh)*34 + tx + kw];
                    float v2 = T[(ty + 16 + kh)*34 + tx + kw];
                    float v3 = T[(ty + 24 + kh)*34 + tx + kw];
#pragma unroll
                    for (int q = 0; q < 4; ++q) {
                        float4 wq = W4[kk*4 + q];
                        acc[q*4+0][0] += v0*wq.x; acc[q*4+0][1] += v1*wq.x;
                        acc[q*4+0][2] += v2*wq.x; acc[q*4+0][3] += v3*wq.x;
                        acc[q*4+1][0] += v0*wq.y; acc[q*4+1][1] += v1*wq.y;
                        acc[q*4+1][2] += v2*wq.y; acc[q*4+1][3] += v3*wq.y;
                        acc[q*4+2][0] += v0*wq.z; acc[q*4+2][1] += v1*wq.z;
                        acc[q*4+2][2] += v2*wq.z; acc[q*4+2][3] += v3*wq.z;
                        acc[q*4+3][0] += v0*wq.w; acc[q*4+3][1] += v1*wq.w;
                        acc[q*4+3][2] += v2*wq.w; acc[q*4+3][3] += v3*wq.w;
                    }
                }
            }
        }
    }

#pragma unroll
    for (int oc = 0; oc < 16; ++oc) {
        int ocg = cg*16 + oc;
        float bv = bias[ocg];
#pragma unroll
        for (int p = 0; p < 4; ++p) {
            int y = by + ty + p*8;
            float v = acc[oc][p] + bv;
            v = fmaxf(v, 0.0f);
            out[((size_t)(img*COUT + ocg)) * HW + y*WW + bx + tx] = v;
        }
    }
}

// ------------------- 1x1 conv 128->16 + leaky_relu(0.2), float2 + MLP8 ----------
__global__ __launch_bounds__(256)
void k_conv4(const float* __restrict__ w4, const float* __restrict__ b4) {
    __shared__ float ws[16*128];
    __shared__ float bs[16];
    int tid = threadIdx.x;
    for (int i = tid; i < 16*128; i += 256) ws[i] = w4[i];
    if (tid < 16) bs[tid] = b4[tid];
    __syncthreads();

    int p2 = blockIdx.x * 256 + tid;         // float2 index (HW/2 per img)
    int img = blockIdx.y;

    float2 acc[16];
#pragma unroll
    for (int c = 0; c < 16; ++c) acc[c] = make_float2(bs[c], bs[c]);

    const float2* in = (const float2*)(g_f128 + (size_t)img*128*HW) + p2;
    for (int ci = 0; ci < 128; ci += 8) {
        float2 v[8];
#pragma unroll
        for (int u = 0; u < 8; ++u)
            v[u] = in[(size_t)(ci + u) * (HW/2)];
#pragma unroll
        for (int c = 0; c < 16; ++c) {
            float ax = acc[c].x, ay = acc[c].y;
#pragma unroll
            for (int u = 0; u < 8; ++u) {
                float wv = ws[c*128 + ci + u];
                ax += wv * v[u].x;
                ay += wv * v[u].y;
            }
            acc[c].x = ax; acc[c].y = ay;
        }
    }
    float2* out = (float2*)(g_f16 + (size_t)img*16*HW) + p2;
#pragma unroll
    for (int c = 0; c < 16; ++c) {
        float2 v = acc[c];
        v.x = (v.x > 0.0f) ? v.x : 0.2f*v.x;
        v.y = (v.y > 0.0f) ? v.y : 0.2f*v.y;
        out[(size_t)c * (HW/2)] = v;
    }
}

// ------------------- unfold k3s3 + per-patch L2 normalize -------------------
__global__ void k_patch() {
    int gw = (blockIdx.x * blockDim.x + threadIdx.x) >> 5;
    int lane = threadIdx.x & 31;
    if (gw >= NIMG * NPATCH) return;
    int img = gw / NPATCH;
    int p   = gw % NPATCH;
    int hq = p / HQ, wq = p % HQ;
    const float* f = g_f16 + (size_t)img*16*HW;

    float v[5];
    float ss = 0.0f;
#pragma unroll
    for (int t = 0; t < 5; ++t) {
        int d = lane + t*32;
        float x = 0.0f;
        if (d < DPATCH) {
            int c = d / 9, kk = d % 9;
            int y = hq*3 + kk/3, xx = wq*3 + kk%3;
            x = f[(size_t)c*HW + y*WW + xx];
        }
        v[t] = x;
        ss += x * x;
    }
#pragma unroll
    for (int m = 16; m; m >>= 1) ss += __shfl_xor_sync(0xffffffffu, ss, m);
    float inv = 1.0f / fmaxf(sqrtf(ss), 1e-12f);
    float* o = g_patch + ((size_t)img*NPATCH + p) * DPATCH;
#pragma unroll
    for (int t = 0; t < 5; ++t) {
        int d = lane + t*32;
        if (d < DPATCH) o[d] = v[t] * inv;
    }
}

// ------------------- correlation GEMM fused with max/argmax over keys -------------------
// grid: (72 m-tiles, 2 batches)  block: 512 (128 queries x 128 keys, 4q x 8k per thread)
#define KPAD 37
#define KTILES 72
__global__ __launch_bounds__(512, 1)
void k_corr(float* __restrict__ out, int out_size) {
    extern __shared__ float4 sm[];
    float4* q_s = sm;                        // 128*36
    float4* k_s = sm + 128*36;               // 2 * 128*KPAD

    const int tid = threadIdx.x;
    const int b = blockIdx.y;
    const int mt = blockIdx.x;
    const float4* qg = (const float4*)(g_patch + (size_t)b       * NPATCH * DPATCH);
    const float4* kg = (const float4*)(g_patch + (size_t)(2 + b) * NPATCH * DPATCH);

    unsigned int q_base = (unsigned int)__cvta_generic_to_shared(q_s);
    unsigned int k_base = (unsigned int)__cvta_generic_to_shared(k_s);

    auto issue_k = [&](int bb, int kt) {
        unsigned int base = k_base + bb * (128*KPAD*16);
        const float4* src = kg + (size_t)kt * 128 * 36;
        for (int i = tid; i < 128*36; i += 512) {
            int r = i / 36, c = i % 36;
            cp_async16(base + (r*KPAD + c)*16, src + i);
        }
    };

    {   // q tile (rows contiguous, no pad)
        const float4* src = qg + (size_t)mt * 128 * 36;
        for (int i = tid; i < 128*36; i += 512)
            cp_async16(q_base + i*16, src + i);
    }
    issue_k(0, 0);
    cp_commit();
    issue_k(1, 1);
    cp_commit();

    const int qgrp = tid >> 4;    // 0..31: owns q rows qgrp*4..+3
    const int kgrp = tid & 15;    // 0..15: owns k rows j*16+kgrp, j=0..7

    float rmax[4];
    int   ridx[4];
#pragma unroll
    for (int i = 0; i < 4; ++i) { rmax[i] = -1e30f; ridx[i] = 0x7fffffff; }

    for (int kt = 0; kt < KTILES; ++kt) {
        cp_wait1();
        __syncthreads();

        const float4* kb = k_s + (kt & 1) * (128*KPAD);

        float acc[8][4];
#pragma unroll
        for (int j = 0; j < 8; ++j)
#pragma unroll
            for (int i = 0; i < 4; ++i) acc[j][i] = 0.0f;

        for (int c = 0; c < 36; ++c) {
            float4 qv[4];
#pragma unroll
            for (int i = 0; i < 4; ++i) qv[i] = q_s[(qgrp*4 + i)*36 + c];
#pragma unroll
            for (int j = 0; j < 8; ++j) {
                float4 kv = kb[(j*16 + kgrp)*KPAD + c];
#pragma unroll
                for (int i = 0; i < 4; ++i)
                    acc[j][i] += qv[i].x*kv.x + qv[i].y*kv.y
                               + qv[i].z*kv.z + qv[i].w*kv.w;
            }
        }

#pragma unroll
        for (int i = 0; i < 4; ++i) {
#pragma unroll
            for (int j = 0; j < 8; ++j) {
                if (acc[j][i] > rmax[i]) { rmax[i] = acc[j][i]; ridx[i] = kt*128 + j*16 + kgrp; }
            }
        }

        __syncthreads();
        if (kt + 2 < KTILES) issue_k(kt & 1, kt + 2);
        cp_commit();
    }

    // reduce across the 16 lanes sharing each q row (kgrp dimension)
#pragma unroll
    for (int i = 0; i < 4; ++i) {
        float bv = rmax[i];
        int   bi = ridx[i];
#pragma unroll
        for (int m = 8; m; m >>= 1) {
            float ov = __shfl_xor_sync(0xffffffffu, bv, m);
            int   oi = __shfl_xor_sync(0xffffffffu, bi, m);
            if (ov > bv || (ov == bv && oi < bi)) { bv = ov; bi = oi; }
        }
        if (kgrp == 0) {
            int m = mt*128 + qgrp*4 + i;
            out[b*NPATCH + m] = bv;
            if (out_size >= 4*NPATCH)
                out[2*NPATCH + b*NPATCH + m] = (float)bi;
        }
    }
}

// ------------------- launch -------------------
extern "C" void kernel_launch(void* const* d_in, const int* in_sizes, int n_in,
                              void* d_out, int out_size) {
    const float* query = (const float*)d_in[0];
    const float* key   = (const float*)d_in[1];
    const float* w1 = (const float*)d_in[3];  const float* b1 = (const float*)d_in[4];
    const float* w2 = (const float*)d_in[5];  const float* b2 = (const float*)d_in[6];
    const float* w3 = (const float*)d_in[7];  const float* b3 = (const float*)d_in[8];
    const float* w4 = (const float*)d_in[9];  const float* b4 = (const float*)d_in[10];
    float* out = (float*)d_out;

    float *p_a, *p_b, *p_128;
    cudaGetSymbolAddress((void**)&p_a,    g_f64a);
    cudaGetSymbolAddress((void**)&p_b,    g_f64b);
    cudaGetSymbolAddress((void**)&p_128,  g_f128);

    const int corr_smem = (128*36 + 2*128*KPAD) * (int)sizeof(float4);  // 225280 B
    cudaFuncSetAttribute(k_corr, cudaFuncAttributeMaxDynamicSharedMemorySize, corr_smem);

    dim3 blk(32, 8);
    k_conv1<<<dim3(9, 9, NIMG*4), blk>>>(query, key, w1, b1, p_a);
    k_conv3x3<64, 64><<<dim3(9, 9, NIMG*4),  blk>>>(p_a, w2, b2, p_b);
    k_conv3x3<64,128><<<dim3(9, 9, NIMG*8),  blk>>>(p_b, w3, b3, p_128);

    k_conv4<<<dim3(HW/512, NIMG), 256>>>(w4, b4);

    k_patch<<<(NIMG*NPATCH*32 + 255)/256, 256>>>();

    k_corr<<<dim3(NPATCH/128, 2), 512, corr_smem>>>(out, out_size);
}

// round 17
// speedup vs baseline: 1.6826x; 1.0285x over previous
#include <cuda_runtime.h>
#include <stdint.h>
#include <math.h>

#define HH 288
#define WW 288
#define HW (HH*WW)          // 82944
#define NIMG 4              // query b0,b1, key b0,b1
#define HQ 96
#define NPATCH (HQ*HQ)      // 9216
#define DPATCH 144

// ------------------- static device scratch (no allocations allowed) -------------------
__device__ float g_f64a[(size_t)NIMG*64*HW];
__device__ float g_f64b[(size_t)NIMG*64*HW];
__device__ float g_f128[(size_t)NIMG*128*HW];
__device__ float g_f16 [(size_t)NIMG*16*HW];
__device__ float g_patch[(size_t)NIMG*NPATCH*DPATCH]; // [img][patch][144]

__constant__ float c_mean[6] = {0.485f, 0.456f, 0.406f, 0.5f, 0.5f, 0.5f};
__constant__ float c_istd[6] = {1.0f/0.229f, 1.0f/0.224f, 1.0f/0.225f,
                                1.0f/0.1f,   1.0f/0.1f,   1.0f/0.1f};

// ---- cp.async helpers ----
__device__ __forceinline__ void cp_async4(unsigned int dst, const void* src, int src_sz) {
    asm volatile("cp.async.ca.shared.global [%0], [%1], 4, %2;"
                 :: "r"(dst), "l"(src), "r"(src_sz));
}
__device__ __forceinline__ void cp_async16(unsigned int dst, const void* src) {
    asm volatile("cp.async.cg.shared.global [%0], [%1], 16;"
                 :: "r"(dst), "l"(src));
}
__device__ __forceinline__ void cp_commit() {
    asm volatile("cp.async.commit_group;");
}
__device__ __forceinline__ void cp_wait1() {
    asm volatile("cp.async.wait_group 1;");
}
__device__ __forceinline__ void cp_wait2() {
    asm volatile("cp.async.wait_group 2;");
}

#define CTILE (34*34)

// ------------------- conv1: 6->64, MeanShift fused at load, ReLU -------------------
// grid: (9, 9, NIMG*4)  block: (32, 8)
__global__ __launch_bounds__(256, 2)
void k_conv1(const float* __restrict__ qsrc, const float* __restrict__ ksrc,
             const float* __restrict__ w, const float* __restrict__ bias,
             float* __restrict__ out) {
    __shared__ float tile[6*CTILE];          // 27.7 KB
    __shared__ float w_s[6*144];             // [cin][kk*16 + oc]

    const int tx = threadIdx.x, ty = threadIdx.y;
    const int tid = ty * 32 + tx;
    const int img = blockIdx.z >> 2;
    const int cg  = blockIdx.z & 3;
    const int bx = blockIdx.x * 32, by = blockIdx.y * 32;

    const float* in = (img < 2) ? (qsrc + (size_t)img*6*HW)
                                : (ksrc + (size_t)(img-2)*6*HW);

#pragma unroll
    for (int t = 0; t < 5; ++t) {
        int i = tid + t*256;
        if (i >= CTILE) break;
        int r = i / 34, c = i - r*34;
        int gy = by - 1 + r, gx = bx - 1 + c;
        bool ok = (gy >= 0) & (gy < HH) & (gx >= 0) & (gx < WW);
        int off = min(max(gy, 0), HH-1)*WW + min(max(gx, 0), WW-1);
#pragma unroll
        for (int ch = 0; ch < 6; ++ch) {
            float v = ok ? (in[(size_t)ch*HW + off] - c_mean[ch]) * c_istd[ch] : 0.0f;
            tile[ch*CTILE + i] = v;
        }
    }
    for (int idx = tid; idx < 6*144; idx += 256) {
        int cin = idx / 144, r = idx % 144;
        int kk = r >> 4, oc = r & 15;
        w_s[idx] = w[((size_t)(cg*16 + oc) * 6 + cin) * 9 + kk];
    }
    __syncthreads();

    float acc[16][4];
#pragma unroll
    for (int oc = 0; oc < 16; ++oc)
#pragma unroll
        for (int p = 0; p < 4; ++p) acc[oc][p] = 0.0f;

#pragma unroll
    for (int ch = 0; ch < 6; ++ch) {
        const float*  T  = &tile[ch*CTILE];
        const float4* W4 = (const float4*)&w_s[ch*144];
#pragma unroll
        for (int kh = 0; kh < 3; ++kh) {
#pragma unroll
            for (int kw = 0; kw < 3; ++kw) {
                const int kk = kh*3 + kw;
                float v0 = T[(ty      + kh)*34 + tx + kw];
                float v1 = T[(ty +  8 + kh)*34 + tx + kw];
                float v2 = T[(ty + 16 + kh)*34 + tx + kw];
                float v3 = T[(ty + 24 + kh)*34 + tx + kw];
#pragma unroll
                for (int q = 0; q < 4; ++q) {
                    float4 wq = W4[kk*4 + q];
                    acc[q*4+0][0] += v0*wq.x; acc[q*4+0][1] += v1*wq.x;
                    acc[q*4+0][2] += v2*wq.x; acc[q*4+0][3] += v3*wq.x;
                    acc[q*4+1][0] += v0*wq.y; acc[q*4+1][1] += v1*wq.y;
                    acc[q*4+1][2] += v2*wq.y; acc[q*4+1][3] += v3*wq.y;
                    acc[q*4+2][0] += v0*wq.z; acc[q*4+2][1] += v1*wq.z;
                    acc[q*4+2][2] += v2*wq.z; acc[q*4+2][3] += v3*wq.z;
                    acc[q*4+3][0] += v0*wq.w; acc[q*4+3][1] += v1*wq.w;
                    acc[q*4+3][2] += v2*wq.w; acc[q*4+3][3] += v3*wq.w;
                }
            }
        }
    }

#pragma unroll
    for (int oc = 0; oc < 16; ++oc) {
        int ocg = cg*16 + oc;
        float bv = bias[ocg];
#pragma unroll
        for (int p = 0; p < 4; ++p) {
            int y = by + ty + p*8;
            float v = acc[oc][p] + bv;
            v = fmaxf(v, 0.0f);
            out[((size_t)(img*64 + ocg)) * HW + y*WW + bx + tx] = v;
        }
    }
}

// ------------------- 3x3 conv, pad=1, ReLU (R7-proven) -------------------
template<int CIN, int COUT>
__global__ __launch_bounds__(256, 2)
void k_conv3x3(const float* __restrict__ in, const float* __restrict__ w,
               const float* __restrict__ bias, float* __restrict__ out) {
    __shared__ float tile[4][2*CTILE];
    __shared__ float w_all[CIN*144];

    const int tx = threadIdx.x, ty = threadIdx.y;
    const int tid = ty * 32 + tx;
    const int groups = COUT / 16;
    const int img = blockIdx.z / groups;
    const int cg  = blockIdx.z % groups;
    const int bx = blockIdx.x * 32, by = blockIdx.y * 32;
    const int S = CIN / 2;

    unsigned int tile_base = (unsigned int)__cvta_generic_to_shared(&tile[0][0]);
    unsigned int w_base    = (unsigned int)__cvta_generic_to_shared(&w_all[0]);

    const bool has5 = (tid < CTILE - 4*256);   // 132
    int  g_off[5];
    int  sz  [5];
    unsigned int s_off[5];
#pragma unroll
    for (int t = 0; t < 5; ++t) {
        int i = tid + t*256;
        if (i >= CTILE) i = 0;
        int r = i / 34, c = i - r*34;
        int gy = by - 1 + r, gx = bx - 1 + c;
        bool ok = (gy >= 0) & (gy < HH) & (gx >= 0) & (gx < WW);
        int cy = min(max(gy, 0), HH-1), cx = min(max(gx, 0), WW-1);
        g_off[t] = cy*WW + cx;
        sz  [t] = ok ? 4 : 0;
        s_off[t] = (unsigned)i * 4u;
    }

    float acc[16][4];
#pragma unroll
    for (int oc = 0; oc < 16; ++oc)
#pragma unroll
        for (int p = 0; p < 4; ++p) acc[oc][p] = 0.0f;

    auto issue_stage = [&](int st) {
        int buf = st & 3;
        const float* inp0 = in + ((size_t)(img*CIN + st*2)) * HW;
#pragma unroll
        for (int ch = 0; ch < 2; ++ch) {
            const float* inp = inp0 + (size_t)ch * HW;
            unsigned int tb = tile_base + (buf*2 + ch) * (CTILE*4);
#pragma unroll
            for (int t = 0; t < 4; ++t)
                cp_async4(tb + s_off[t], inp + g_off[t], sz[t]);
            if (has5)
                cp_async4(tb + s_off[4], inp + g_off[4], sz[4]);
        }
    };

    for (int idx = tid; idx < CIN*144; idx += 256) {
        int cin = idx / 144, r = idx % 144;
        int kk = r >> 4, oc = r & 15;
        cp_async4(w_base + idx*4, w + ((size_t)(cg*16 + oc) * CIN + cin) * 9 + kk, 4);
    }
    issue_stage(0);
    cp_commit();
    if (S > 1) issue_stage(1);
    cp_commit();
    if (S > 2) issue_stage(2);
    cp_commit();

    for (int s = 0; s < S; ++s) {
        cp_wait2();
        __syncthreads();
        if (s + 3 < S) issue_stage(s + 3);
        cp_commit();

        const int buf = s & 3;
#pragma unroll
        for (int ch = 0; ch < 2; ++ch) {
            const float*  T  = &tile[buf][ch*CTILE];
            const float4* W4 = (const float4*)&w_all[(s*2 + ch)*144];
#pragma unroll
            for (int kh = 0; kh < 3; ++kh) {
#pragma unroll
                for (int kw = 0; kw < 3; ++kw) {
                    const int kk = kh*3 + kw;
                    float v0 = T[(ty      + kh)*34 + tx + kw];
                    float v1 = T[(ty +  8 + kh)*34 + tx + kw];
                    float v2 = T[(ty + 16 + kh)*34 + tx + kw];
                    float v3 = T[(ty + 24 + kh)*34 + tx + kw];
#pragma unroll
                    for (int q = 0; q < 4; ++q) {
                        float4 wq = W4[kk*4 + q];
                        acc[q*4+0][0] += v0*wq.x; acc[q*4+0][1] += v1*wq.x;
                        acc[q*4+0][2] += v2*wq.x; acc[q*4+0][3] += v3*wq.x;
                        acc[q*4+1][0] += v0*wq.y; acc[q*4+1][1] += v1*wq.y;
                        acc[q*4+1][2] += v2*wq.y; acc[q*4+1][3] += v3*wq.y;
                        acc[q*4+2][0] += v0*wq.z; acc[q*4+2][1] += v1*wq.z;
                        acc[q*4+2][2] += v2*wq.z; acc[q*4+2][3] += v3*wq.z;
                        acc[q*4+3][0] += v0*wq.w; acc[q*4+3][1] += v1*wq.w;
                        acc[q*4+3][2] += v2*wq.w; acc[q*4+3][3] += v3*wq.w;
                    }
                }
            }
        }
    }

#pragma unroll
    for (int oc = 0; oc < 16; ++oc) {
        int ocg = cg*16 + oc;
        float bv = bias[ocg];
#pragma unroll
        for (int p = 0; p < 4; ++p) {
            int y = by + ty + p*8;
            float v = acc[oc][p] + bv;
            v = fmaxf(v, 0.0f);
            out[((size_t)(img*COUT + ocg)) * HW + y*WW + bx + tx] = v;
        }
    }
}

// ------------------- 1x1 conv 128->16 + leaky_relu(0.2), float2 + MLP8 ----------
__global__ __launch_bounds__(256)
void k_conv4(const float* __restrict__ w4, const float* __restrict__ b4) {
    __shared__ float ws[16*128];
    __shared__ float bs[16];
    int tid = threadIdx.x;
    for (int i = tid; i < 16*128; i += 256) ws[i] = w4[i];
    if (tid < 16) bs[tid] = b4[tid];
    __syncthreads();

    int p2 = blockIdx.x * 256 + tid;         // float2 index (HW/2 per img)
    int img = blockIdx.y;

    float2 acc[16];
#pragma unroll
    for (int c = 0; c < 16; ++c) acc[c] = make_float2(bs[c], bs[c]);

    const float2* in = (const float2*)(g_f128 + (size_t)img*128*HW) + p2;
    for (int ci = 0; ci < 128; ci += 8) {
        float2 v[8];
#pragma unroll
        for (int u = 0; u < 8; ++u)
            v[u] = in[(size_t)(ci + u) * (HW/2)];
#pragma unroll
        for (int c = 0; c < 16; ++c) {
            float ax = acc[c].x, ay = acc[c].y;
#pragma unroll
            for (int u = 0; u < 8; ++u) {
                float wv = ws[c*128 + ci + u];
                ax += wv * v[u].x;
                ay += wv * v[u].y;
            }
            acc[c].x = ax; acc[c].y = ay;
        }
    }
    float2* out = (float2*)(g_f16 + (size_t)img*16*HW) + p2;
#pragma unroll
    for (int c = 0; c < 16; ++c) {
        float2 v = acc[c];
        v.x = (v.x > 0.0f) ? v.x : 0.2f*v.x;
        v.y = (v.y > 0.0f) ? v.y : 0.2f*v.y;
        out[(size_t)c * (HW/2)] = v;
    }
}

// ------------------- unfold k3s3 + per-patch L2 normalize -------------------
__global__ void k_patch() {
    int gw = (blockIdx.x * blockDim.x + threadIdx.x) >> 5;
    int lane = threadIdx.x & 31;
    if (gw >= NIMG * NPATCH) return;
    int img = gw / NPATCH;
    int p   = gw % NPATCH;
    int hq = p / HQ, wq = p % HQ;
    const float* f = g_f16 + (size_t)img*16*HW;

    float v[5];
    float ss = 0.0f;
#pragma unroll
    for (int t = 0; t < 5; ++t) {
        int d = lane + t*32;
        float x = 0.0f;
        if (d < DPATCH) {
            int c = d / 9, kk = d % 9;
            int y = hq*3 + kk/3, xx = wq*3 + kk%3;
            x = f[(size_t)c*HW + y*WW + xx];
        }
        v[t] = x;
        ss += x * x;
    }
#pragma unroll
    for (int m = 16; m; m >>= 1) ss += __shfl_xor_sync(0xffffffffu, ss, m);
    float inv = 1.0f / fmaxf(sqrtf(ss), 1e-12f);
    float* o = g_patch + ((size_t)img*NPATCH + p) * DPATCH;
#pragma unroll
    for (int t = 0; t < 5; ++t) {
        int d = lane + t*32;
        if (d < DPATCH) o[d] = v[t] * inv;
    }
}

// ------------------- correlation GEMM fused with max/argmax over keys -------------------
// PROVEN R7/R13 version: 256 threads, 128q x 128k tile, 8x8 per thread.
#define KPAD 37
#define KTILES 72
__global__ __launch_bounds__(256, 1)
void k_corr(float* __restrict__ out, int out_size) {
    extern __shared__ float4 sm[];
    float4* q_s = sm;                        // 128*36
    float4* k_s = sm + 128*36;               // 2 * 128*KPAD

    const int tid = threadIdx.x;
    const int b = blockIdx.y;
    const int mt = blockIdx.x;
    const float4* qg = (const float4*)(g_patch + (size_t)b       * NPATCH * DPATCH);
    const float4* kg = (const float4*)(g_patch + (size_t)(2 + b) * NPATCH * DPATCH);

    unsigned int q_base = (unsigned int)__cvta_generic_to_shared(q_s);
    unsigned int k_base = (unsigned int)__cvta_generic_to_shared(k_s);

    auto issue_k = [&](int bb, int kt) {
        unsigned int base = k_base + bb * (128*KPAD*16);
        const float4* src = kg + (size_t)kt * 128 * 36;
        for (int i = tid; i < 128*36; i += 256) {
            int r = i / 36, c = i % 36;
            cp_async16(base + (r*KPAD + c)*16, src + i);
        }
    };

    {   // q tile (rows contiguous, no pad)
        const float4* src = qg + (size_t)mt * 128 * 36;
        for (int i = tid; i < 128*36; i += 256)
            cp_async16(q_base + i*16, src + i);
    }
    issue_k(0, 0);
    cp_commit();
    issue_k(1, 1);
    cp_commit();

    const int qgrp = tid >> 4;    // 0..15: owns q rows qgrp*8..+7
    const int kgrp = tid & 15;    // 0..15: owns k rows j*16+kgrp, j=0..7

    float rmax[8];
    int   ridx[8];
#pragma unroll
    for (int i = 0; i < 8; ++i) { rmax[i] = -1e30f; ridx[i] = 0x7fffffff; }

    for (int kt = 0; kt < KTILES; ++kt) {
        cp_wait1();
        __syncthreads();

        const float4* kb = k_s + (kt & 1) * (128*KPAD);

        float acc[8][8];
#pragma unroll
        for (int j = 0; j < 8; ++j)
#pragma unroll
            for (int i = 0; i < 8; ++i) acc[j][i] = 0.0f;

        for (int c = 0; c < 36; ++c) {
            float4 qv[8];
#pragma unroll
            for (int i = 0; i < 8; ++i) qv[i] = q_s[(qgrp*8 + i)*36 + c];
#pragma unroll
            for (int j = 0; j < 8; ++j) {
                float4 kv = kb[(j*16 + kgrp)*KPAD + c];
#pragma unroll
                for (int i = 0; i < 8; ++i)
                    acc[j][i] += qv[i].x*kv.x + qv[i].y*kv.y
                               + qv[i].z*kv.z + qv[i].w*kv.w;
            }
        }

#pragma unroll
        for (int i = 0; i < 8; ++i) {
#pragma unroll
            for (int j = 0; j < 8; ++j) {
                if (acc[j][i] > rmax[i]) { rmax[i] = acc[j][i]; ridx[i] = kt*128 + j*16 + kgrp; }
            }
        }

        __syncthreads();
        if (kt + 2 < KTILES) issue_k(kt & 1, kt + 2);
        cp_commit();
    }

#pragma unroll
    for (int i = 0; i < 8; ++i) {
        float bv = rmax[i];
        int   bi = ridx[i];
#pragma unroll
        for (int m = 8; m; m >>= 1) {
            float ov = __shfl_xor_sync(0xffffffffu, bv, m);
            int   oi = __shfl_xor_sync(0xffffffffu, bi, m);
            if (ov > bv || (ov == bv && oi < bi)) { bv = ov; bi = oi; }
        }
        if (kgrp == 0) {
            int m = mt*128 + qgrp*8 + i;
            out[b*NPATCH + m] = bv;
            if (out_size >= 4*NPATCH)
                out[2*NPATCH + b*NPATCH + m] = (float)bi;
        }
    }
}

// ------------------- launch -------------------
extern "C" void kernel_launch(void* const* d_in, const int* in_sizes, int n_in,
                              void* d_out, int out_size) {
    const float* query = (const float*)d_in[0];
    const float* key   = (const float*)d_in[1];
    const float* w1 = (const float*)d_in[3];  const float* b1 = (const float*)d_in[4];
    const float* w2 = (const float*)d_in[5];  const float* b2 = (const float*)d_in[6];
    const float* w3 = (const float*)d_in[7];  const float* b3 = (const float*)d_in[8];
    const float* w4 = (const float*)d_in[9];  const float* b4 = (const float*)d_in[10];
    float* out = (float*)d_out;

    float *p_a, *p_b, *p_128;
    cudaGetSymbolAddress((void**)&p_a,    g_f64a);
    cudaGetSymbolAddress((void**)&p_b,    g_f64b);
    cudaGetSymbolAddress((void**)&p_128,  g_f128);

    const int corr_smem = (128*36 + 2*128*KPAD) * (int)sizeof(float4);  // 225280 B
    cudaFuncSetAttribute(k_corr, cudaFuncAttributeMaxDynamicSharedMemorySize, corr_smem);

    dim3 blk(32, 8);
    k_conv1<<<dim3(9, 9, NIMG*4), blk>>>(query, key, w1, b1, p_a);
    k_conv3x3<64, 64><<<dim3(9, 9, NIMG*4),  blk>>>(p_a, w2, b2, p_b);
    k_conv3x3<64,128><<<dim3(9, 9, NIMG*8),  blk>>>(p_b, w3, b3, p_128);

    k_conv4<<<dim3(HW/512, NIMG), 256>>>(w4, b4);

    k_patch<<<(NIMG*NPATCH*32 + 255)/256, 256>>>();

    k_corr<<<dim3(NPATCH/128, 2), 256, corr_smem>>>(out, out_size);
}